// round 1
// baseline (speedup 1.0000x reference)
#include <cuda_runtime.h>
#include <cstdint>
#include <cstddef>

// Problem constants
#define kB  2
#define kS  2048
#define kD  1024
#define kH  16
#define kHD 64
#define kM  (kB * kS)            // 4096 rows
#define INV_SCALE 0.125f         // 1/sqrt(64)

// Scratch (module globals — no runtime allocation)
__device__ float g_q[(size_t)kB * kS * kD];
__device__ float g_k[(size_t)kB * kS * kD];
__device__ float g_v[(size_t)kB * kS * kD];
__device__ float g_ao[(size_t)kB * kS * kD];
__device__ float g_attn_fb[(size_t)kB * kH * kS * kS];  // fallback if out layout differs

// ---------------------------------------------------------------------------
// GEMM: C(128x64 tile) = X @ W^T + bias.  X:(kM,kD) row-major, W:(N,kD) row-major.
// 256 threads; thread (lane,w) owns rows {lane+32i} x cols {w+8j}.
// MODE 0: store head-major (b,h,s,hd) (N-tile of 64 == exactly one head)
// MODE 1: store plain row-major
// ---------------------------------------------------------------------------
template <int MODE>
__global__ void __launch_bounds__(256, 2) proj_kernel(
    const float* __restrict__ X, const float* __restrict__ W,
    const float* __restrict__ bias, float* __restrict__ out) {
  extern __shared__ float sm[];
  float(*As)[68] = (float(*)[68])sm;               // 128 x 68
  float(*Ws)[68] = (float(*)[68])(sm + 128 * 68);  // 64 x 68
  const int t = threadIdx.x, lane = t & 31, w = t >> 5;
  const int i0 = blockIdx.y * 128, j0 = blockIdx.x * 64;

  float acc[4][8];
#pragma unroll
  for (int ii = 0; ii < 4; ii++)
#pragma unroll
    for (int jj = 0; jj < 8; jj++) acc[ii][jj] = 0.f;

  for (int kc = 0; kc < kD; kc += 64) {
    __syncthreads();
#pragma unroll
    for (int p = 0; p < 8; p++) {
      int f = t + p * 256, r = f >> 4, c4 = f & 15;
      *(float4*)&As[r][c4 * 4] =
          *(const float4*)(X + (size_t)(i0 + r) * kD + kc + c4 * 4);
    }
#pragma unroll
    for (int p = 0; p < 4; p++) {
      int f = t + p * 256, r = f >> 4, c4 = f & 15;
      *(float4*)&Ws[r][c4 * 4] =
          *(const float4*)(W + (size_t)(j0 + r) * kD + kc + c4 * 4);
    }
    __syncthreads();
#pragma unroll
    for (int k = 0; k < 64; k += 4) {
      float4 af[4], bf[8];
#pragma unroll
      for (int ii = 0; ii < 4; ii++) af[ii] = *(float4*)&As[lane + 32 * ii][k];
#pragma unroll
      for (int jj = 0; jj < 8; jj++) bf[jj] = *(float4*)&Ws[w + 8 * jj][k];
#pragma unroll
      for (int ii = 0; ii < 4; ii++)
#pragma unroll
        for (int jj = 0; jj < 8; jj++) {
          acc[ii][jj] = fmaf(af[ii].x, bf[jj].x, acc[ii][jj]);
          acc[ii][jj] = fmaf(af[ii].y, bf[jj].y, acc[ii][jj]);
          acc[ii][jj] = fmaf(af[ii].z, bf[jj].z, acc[ii][jj]);
          acc[ii][jj] = fmaf(af[ii].w, bf[jj].w, acc[ii][jj]);
        }
    }
  }
  __syncthreads();
#pragma unroll
  for (int ii = 0; ii < 4; ii++)
#pragma unroll
    for (int jj = 0; jj < 8; jj++) As[lane + 32 * ii][w + 8 * jj] = acc[ii][jj];
  __syncthreads();
  const int h0 = j0 >> 6;
#pragma unroll
  for (int p = 0; p < 8; p++) {
    int f = t + p * 256, r = f >> 4, c4 = f & 15;
    float4 v = *(float4*)&As[r][c4 * 4];
    float4 bv = *(const float4*)(bias + j0 + c4 * 4);
    v.x += bv.x; v.y += bv.y; v.z += bv.z; v.w += bv.w;
    int i = i0 + r;
    if (MODE == 0) {
      int bb = i >> 11, s = i & 2047;
      *(float4*)(out + ((size_t)(bb * kH + h0) * kS + s) * kHD + c4 * 4) = v;
    } else {
      *(float4*)(out + (size_t)i * kD + j0 + c4 * 4) = v;
    }
  }
}

// ---------------------------------------------------------------------------
// Fused causal attention per (q-tile of 128, bh):
//   Phase A: S = QK^T/8, stage raw scores to attn gmem (coalesced), online m,l
//   Reduce m,l across warps; zero-fill fully-masked columns
//   Phase B: reload staged scores (L2-hot), P = exp(s-m)/l, write final P,
//            accumulate O += P @ V; store O in (b,s,D) layout for final proj.
// ---------------------------------------------------------------------------
__global__ void __launch_bounds__(256, 2) attn_kernel(float* __restrict__ attnW) {
  extern __shared__ float sm[];
  float(*Qs)[68] = (float(*)[68])sm;                // 128 x 68
  float(*Ks)[68] = (float(*)[68])(sm + 128 * 68);   // 64 x 68
  float(*Vt)[68] = (float(*)[68])(sm + 192 * 68);   // 64 x 68 (transposed: [dv][k])
  float(*Ps)[68] = (float(*)[68])(sm + 256 * 68);   // 128 x 68
  float* m_s  = sm + 384 * 68;                      // 128
  float* li_s = m_s + 128;                          // 128
  float* redm = (float*)Ps;                         // overlay (used between phases)
  float* redl = redm + 1024;

  const int t = threadIdx.x, lane = t & 31, w = t >> 5;
  const int q0 = blockIdx.x * 128;
  const int bh = blockIdx.y;
  const int b = bh >> 4, h = bh & 15;
  const float* qp = g_q + (size_t)bh * kS * kHD;
  const float* kp = g_k + (size_t)bh * kS * kHD;
  const float* vp = g_v + (size_t)bh * kS * kHD;
  float* aw = attnW + (size_t)bh * kS * kS;

#pragma unroll
  for (int p = 0; p < 8; p++) {
    int f = t + p * 256, r = f >> 4, c4 = f & 15;
    *(float4*)&Qs[r][c4 * 4] =
        *(const float4*)(qp + (size_t)(q0 + r) * kHD + c4 * 4);
  }

  float m_r[4], l_r[4];
#pragma unroll
  for (int ii = 0; ii < 4; ii++) { m_r[ii] = -1e30f; l_r[ii] = 0.f; }

  const int nkt = q0 / 64 + 2;  // k-tiles up to & including the diagonal tile

  // ---- Phase A ----
  for (int kt = 0; kt < nkt; kt++) {
    __syncthreads();
#pragma unroll
    for (int p = 0; p < 4; p++) {
      int f = t + p * 256, r = f >> 4, c4 = f & 15;
      *(float4*)&Ks[r][c4 * 4] =
          *(const float4*)(kp + (size_t)(kt * 64 + r) * kHD + c4 * 4);
    }
    __syncthreads();
    float sv[4][8];
#pragma unroll
    for (int ii = 0; ii < 4; ii++)
#pragma unroll
      for (int jj = 0; jj < 8; jj++) sv[ii][jj] = 0.f;
#pragma unroll
    for (int k = 0; k < 64; k += 4) {
      float4 af[4], bf[8];
#pragma unroll
      for (int ii = 0; ii < 4; ii++) af[ii] = *(float4*)&Qs[lane + 32 * ii][k];
#pragma unroll
      for (int jj = 0; jj < 8; jj++) bf[jj] = *(float4*)&Ks[w + 8 * jj][k];
#pragma unroll
      for (int ii = 0; ii < 4; ii++)
#pragma unroll
        for (int jj = 0; jj < 8; jj++) {
          sv[ii][jj] = fmaf(af[ii].x, bf[jj].x, sv[ii][jj]);
          sv[ii][jj] = fmaf(af[ii].y, bf[jj].y, sv[ii][jj]);
          sv[ii][jj] = fmaf(af[ii].z, bf[jj].z, sv[ii][jj]);
          sv[ii][jj] = fmaf(af[ii].w, bf[jj].w, sv[ii][jj]);
        }
    }
#pragma unroll
    for (int ii = 0; ii < 4; ii++) {
      int q = q0 + lane + 32 * ii;
      float tmax = -1e30f;
#pragma unroll
      for (int jj = 0; jj < 8; jj++) {
        int kcol = kt * 64 + w + 8 * jj;
        float s = sv[ii][jj] * INV_SCALE;
        if (kcol > q) s = -1e30f;  // causal
        sv[ii][jj] = s;
        tmax = fmaxf(tmax, s);
        Ps[lane + 32 * ii][w + 8 * jj] = s;
      }
      float mn = fmaxf(m_r[ii], tmax);
      float corr = __expf(m_r[ii] - mn);
      float ps = 0.f;
#pragma unroll
      for (int jj = 0; jj < 8; jj++) ps += __expf(sv[ii][jj] - mn);
      l_r[ii] = l_r[ii] * corr + ps;
      m_r[ii] = mn;
    }
    __syncthreads();
#pragma unroll
    for (int p = 0; p < 8; p++) {  // stage raw scores (coalesced)
      int f = t + p * 256, r = f >> 4, c4 = f & 15;
      *(float4*)(aw + (size_t)(q0 + r) * kS + kt * 64 + c4 * 4) =
          *(float4*)&Ps[r][c4 * 4];
    }
  }
  __syncthreads();

  // ---- reduce m,l across the 8 warps ----
#pragma unroll
  for (int ii = 0; ii < 4; ii++) {
    redm[w * 128 + lane + 32 * ii] = m_r[ii];
    redl[w * 128 + lane + 32 * ii] = l_r[ii];
  }
  __syncthreads();
  if (t < 128) {
    float m = -1e30f;
#pragma unroll
    for (int ww = 0; ww < 8; ww++) m = fmaxf(m, redm[ww * 128 + t]);
    float l = 0.f;
#pragma unroll
    for (int ww = 0; ww < 8; ww++)
      l += redl[ww * 128 + t] * __expf(redm[ww * 128 + t] - m);
    m_s[t] = m;
    li_s[t] = 1.f / l;
  }
  __syncthreads();

  // ---- zero-fill fully masked columns [nkt*64, kS) ----
  {
    int width4 = (kS - nkt * 64) >> 2;
    if (width4 > 0) {
      float4 z = make_float4(0.f, 0.f, 0.f, 0.f);
      for (int f = t; f < 128 * width4; f += 256) {
        int r = f / width4, c = f - r * width4;
        *(float4*)(aw + (size_t)(q0 + r) * kS + nkt * 64 + c * 4) = z;
      }
    }
  }

  float o[4][8];
#pragma unroll
  for (int ii = 0; ii < 4; ii++)
#pragma unroll
    for (int jj = 0; jj < 8; jj++) o[ii][jj] = 0.f;

  // ---- Phase B ----
  for (int kt = 0; kt < nkt; kt++) {
    __syncthreads();
    // load V tile transposed: Vt[dv][k]
#pragma unroll
    for (int p = 0; p < 4; p++) {
      int idx = t + p * 256;
      int dv = idx & 63, kq = idx >> 6;
#pragma unroll
      for (int e = 0; e < 4; e++)
        Vt[dv][kq * 4 + e] = vp[(size_t)(kt * 64 + kq * 4 + e) * kHD + dv];
    }
    // reload staged scores (L2-hot), normalize, write final P
#pragma unroll
    for (int p = 0; p < 8; p++) {
      int f = t + p * 256, r = f >> 4, c4 = f & 15;
      size_t off = (size_t)(q0 + r) * kS + kt * 64 + c4 * 4;
      float4 s4 = *(const float4*)(aw + off);
      float m = m_s[r], li = li_s[r];
      float4 pv;
      pv.x = __expf(s4.x - m) * li;
      pv.y = __expf(s4.y - m) * li;
      pv.z = __expf(s4.z - m) * li;
      pv.w = __expf(s4.w - m) * li;
      *(float4*)&Ps[r][c4 * 4] = pv;
      *(float4*)(aw + off) = pv;
    }
    __syncthreads();
#pragma unroll
    for (int k = 0; k < 64; k += 4) {
      float4 af[4], bf[8];
#pragma unroll
      for (int ii = 0; ii < 4; ii++) af[ii] = *(float4*)&Ps[lane + 32 * ii][k];
#pragma unroll
      for (int jj = 0; jj < 8; jj++) bf[jj] = *(float4*)&Vt[w + 8 * jj][k];
#pragma unroll
      for (int ii = 0; ii < 4; ii++)
#pragma unroll
        for (int jj = 0; jj < 8; jj++) {
          o[ii][jj] = fmaf(af[ii].x, bf[jj].x, o[ii][jj]);
          o[ii][jj] = fmaf(af[ii].y, bf[jj].y, o[ii][jj]);
          o[ii][jj] = fmaf(af[ii].z, bf[jj].z, o[ii][jj]);
          o[ii][jj] = fmaf(af[ii].w, bf[jj].w, o[ii][jj]);
        }
    }
  }
  __syncthreads();
#pragma unroll
  for (int ii = 0; ii < 4; ii++)
#pragma unroll
    for (int jj = 0; jj < 8; jj++) Qs[lane + 32 * ii][w + 8 * jj] = o[ii][jj];
  __syncthreads();
#pragma unroll
  for (int p = 0; p < 8; p++) {
    int f = t + p * 256, r = f >> 4, c4 = f & 15;
    *(float4*)(g_ao + ((size_t)(b * kS + q0 + r)) * kD + h * kHD + c4 * 4) =
        *(float4*)&Qs[r][c4 * 4];
  }
}

// ---------------------------------------------------------------------------
extern "C" void kernel_launch(void* const* d_in, const int* in_sizes, int n_in,
                              void* d_out, int out_size) {
  (void)in_sizes; (void)n_in;
  const float* query = (const float*)d_in[0];
  const float* key_  = (const float*)d_in[1];
  const float* value = (const float*)d_in[2];
  // d_in[3] = causal mask (bool) — implied by indices, not read
  const float* Wq = (const float*)d_in[4];
  const float* bq = (const float*)d_in[5];
  const float* Wk = (const float*)d_in[6];
  const float* bk = (const float*)d_in[7];
  const float* Wv = (const float*)d_in[8];
  const float* bv = (const float*)d_in[9];
  const float* Wo = (const float*)d_in[10];
  const float* bo = (const float*)d_in[11];
  float* out = (float*)d_out;

  float *pq, *pk, *pv, *pao, *pfb;
  cudaGetSymbolAddress((void**)&pq, g_q);
  cudaGetSymbolAddress((void**)&pk, g_k);
  cudaGetSymbolAddress((void**)&pv, g_v);
  cudaGetSymbolAddress((void**)&pao, g_ao);
  cudaGetSymbolAddress((void**)&pfb, g_attn_fb);

  const size_t outElems = (size_t)kB * kS * kD;
  const size_t attnElems = (size_t)kB * kH * kS * kS;
  float* attnW = ((size_t)out_size >= outElems + attnElems)
                     ? (out + outElems)   // tuple flattened: [output, attn_weights]
                     : pfb;               // fallback scratch

  const int PROJ_SMEM = (128 + 64) * 68 * 4;        // 52224 B
  const int ATTN_SMEM = (384 * 68 + 256) * 4;       // 105472 B
  cudaFuncSetAttribute(proj_kernel<0>,
                       cudaFuncAttributeMaxDynamicSharedMemorySize, PROJ_SMEM);
  cudaFuncSetAttribute(proj_kernel<1>,
                       cudaFuncAttributeMaxDynamicSharedMemorySize, PROJ_SMEM);
  cudaFuncSetAttribute(attn_kernel,
                       cudaFuncAttributeMaxDynamicSharedMemorySize, ATTN_SMEM);

  dim3 gproj(kD / 64, kM / 128);   // (16, 32)
  dim3 gattn(kS / 128, kB * kH);   // (16, 32)

  proj_kernel<0><<<gproj, 256, PROJ_SMEM>>>(query, Wq, bq, pq);
  proj_kernel<0><<<gproj, 256, PROJ_SMEM>>>(key_, Wk, bk, pk);
  proj_kernel<0><<<gproj, 256, PROJ_SMEM>>>(value, Wv, bv, pv);
  attn_kernel<<<gattn, 256, ATTN_SMEM>>>(attnW);
  proj_kernel<1><<<gproj, 256, PROJ_SMEM>>>(pao, Wo, bo, out);
}

// round 4
// speedup vs baseline: 1.4100x; 1.4100x over previous
#include <cuda_runtime.h>
#include <cuda_bf16.h>
#include <cstdint>
#include <cstddef>

// Problem constants
#define kB  2
#define kS  2048
#define kD  1024
#define kH  16
#define kHD 64
#define kM  (kB * kS)            // 4096 rows
#define INV_SCALE 0.125f         // 1/sqrt(64)

// Scratch (module globals — no runtime allocation)
__device__ float g_q[(size_t)kB * kS * kD];
__device__ float g_k[(size_t)kB * kS * kD];
__device__ float g_v[(size_t)kB * kS * kD];
__device__ float g_ao[(size_t)kB * kS * kD];
__device__ float g_attn_fb[(size_t)kB * kH * kS * kS];  // fallback if out layout differs
__device__ __nv_bfloat16 g_xhi[(size_t)kM * kD];
__device__ __nv_bfloat16 g_xlo[(size_t)kM * kD];
__device__ __nv_bfloat16 g_whi[(size_t)kD * kD];
__device__ __nv_bfloat16 g_wlo[(size_t)kD * kD];

// ---------------------------------------------------------------------------
// helpers
// ---------------------------------------------------------------------------
__device__ __forceinline__ uint32_t smem_u32(const void* p) {
  uint32_t a;
  asm("{ .reg .u64 t; cvta.to.shared.u64 t, %1; cvt.u32.u64 %0, t; }"
      : "=r"(a) : "l"(p));
  return a;
}

__device__ __forceinline__ void ldsm_x4(uint32_t& r0, uint32_t& r1,
                                        uint32_t& r2, uint32_t& r3,
                                        uint32_t addr) {
  asm volatile("ldmatrix.sync.aligned.m8n8.x4.shared.b16 {%0,%1,%2,%3}, [%4];"
               : "=r"(r0), "=r"(r1), "=r"(r2), "=r"(r3) : "r"(addr));
}

__device__ __forceinline__ void mma_bf16(float* c, const uint32_t* a,
                                         const uint32_t* b) {
  asm volatile(
      "mma.sync.aligned.m16n8k16.row.col.f32.bf16.bf16.f32 "
      "{%0,%1,%2,%3}, {%4,%5,%6,%7}, {%8,%9}, {%0,%1,%2,%3};"
      : "+f"(c[0]), "+f"(c[1]), "+f"(c[2]), "+f"(c[3])
      : "r"(a[0]), "r"(a[1]), "r"(a[2]), "r"(a[3]), "r"(b[0]), "r"(b[1]));
}

// ---------------------------------------------------------------------------
// fp32 -> (bf16 hi, bf16 lo) split conversion, vectorized x4
// ---------------------------------------------------------------------------
__global__ void cvt_split(const float* __restrict__ x,
                          __nv_bfloat16* __restrict__ hi,
                          __nv_bfloat16* __restrict__ lo, int n4) {
  int i = blockIdx.x * blockDim.x + threadIdx.x;
  if (i >= n4) return;
  float4 v = ((const float4*)x)[i];
  __nv_bfloat16 h0 = __float2bfloat16_rn(v.x);
  __nv_bfloat16 h1 = __float2bfloat16_rn(v.y);
  __nv_bfloat16 h2 = __float2bfloat16_rn(v.z);
  __nv_bfloat16 h3 = __float2bfloat16_rn(v.w);
  __nv_bfloat16 l0 = __float2bfloat16_rn(v.x - __bfloat162float(h0));
  __nv_bfloat16 l1 = __float2bfloat16_rn(v.y - __bfloat162float(h1));
  __nv_bfloat16 l2 = __float2bfloat16_rn(v.z - __bfloat162float(h2));
  __nv_bfloat16 l3 = __float2bfloat16_rn(v.w - __bfloat162float(h3));
  __nv_bfloat162* hp = (__nv_bfloat162*)hi;
  __nv_bfloat162* lp = (__nv_bfloat162*)lo;
  __nv_bfloat162 a, b2;
  a.x = h0; a.y = h1;  hp[i * 2] = a;
  a.x = h2; a.y = h3;  hp[i * 2 + 1] = a;
  b2.x = l0; b2.y = l1; lp[i * 2] = b2;
  b2.x = l2; b2.y = l3; lp[i * 2 + 1] = b2;
}

// ---------------------------------------------------------------------------
// mma.sync split-bf16 GEMM: C(128x64 tile) = X @ W^T + bias
//   3 passes per k-step: hi*hi + hi*lo + lo*hi (lo*lo dropped, ~2^-18).
// 8 warps: warp grid 4(M) x 2(N); warp tile 32x32 = 2 m16 x 4 n8 mma tiles.
// smem (bf16, rows padded to 72 elems = 144 B -> conflict-free ldmatrix):
//   Ahi[128][72] @0, Alo @18432, Bhi[64][72] @36864, Blo @46080 (55296 B)
// MODE 0: store head-major (b,h,s,hd).  MODE 1: plain row-major.
// ---------------------------------------------------------------------------
#define PROJ_SMEM_B 55296

template <int MODE>
__global__ void __launch_bounds__(256, 2) proj_mma(
    const __nv_bfloat16* __restrict__ Xhi, const __nv_bfloat16* __restrict__ Xlo,
    const __nv_bfloat16* __restrict__ Whi, const __nv_bfloat16* __restrict__ Wlo,
    const float* __restrict__ bias, float* __restrict__ out) {
  extern __shared__ char smc[];
  const uint32_t sb = smem_u32(smc);
  const int t = threadIdx.x, lane = t & 31, w = t >> 5;
  const int wm = w & 3, wn = w >> 2;          // warp grid 4x2
  const int i0 = blockIdx.y * 128, j0 = blockIdx.x * 64;
  const int q = lane >> 3, rr = lane & 7, g = lane >> 2, tg = lane & 3;

  // per-thread ldmatrix byte offsets (within each operand region)
  uint32_t a_off[2], b_off[2];
#pragma unroll
  for (int mt = 0; mt < 2; mt++)
    a_off[mt] = (uint32_t)((wm * 32 + mt * 16 + (q & 1) * 8 + rr) * 144 +
                           (q >> 1) * 16);
#pragma unroll
  for (int gg = 0; gg < 2; gg++)
    b_off[gg] = (uint32_t)((wn * 32 + gg * 16 + (q >> 1) * 8 + rr) * 144 +
                           (q & 1) * 16);

  float acc[2][4][4];
#pragma unroll
  for (int mt = 0; mt < 2; mt++)
#pragma unroll
    for (int nt = 0; nt < 4; nt++)
#pragma unroll
      for (int e = 0; e < 4; e++) acc[mt][nt][e] = 0.f;

  for (int kc = 0; kc < 16; kc++) {
    const int col0 = kc * 64;
    __syncthreads();
    // load A tiles (128x64 hi + lo)
#pragma unroll
    for (int p = 0; p < 4; p++) {
      int idx = t + p * 256, r = idx >> 3, c8 = idx & 7;
      uint32_t dst = (uint32_t)(r * 144 + c8 * 16);
      const size_t so = (size_t)(i0 + r) * kD + col0 + c8 * 8;
      *(uint4*)(smc + dst) = *(const uint4*)(Xhi + so);
      *(uint4*)(smc + 18432 + dst) = *(const uint4*)(Xlo + so);
    }
    // load B tiles (64x64 hi + lo)
#pragma unroll
    for (int p = 0; p < 2; p++) {
      int idx = t + p * 256, r = idx >> 3, c8 = idx & 7;
      uint32_t dst = (uint32_t)(r * 144 + c8 * 16);
      const size_t so = (size_t)(j0 + r) * kD + col0 + c8 * 8;
      *(uint4*)(smc + 36864 + dst) = *(const uint4*)(Whi + so);
      *(uint4*)(smc + 46080 + dst) = *(const uint4*)(Wlo + so);
    }
    __syncthreads();

#pragma unroll
    for (int ks = 0; ks < 4; ks++) {
      const uint32_t kbo = ks * 32;
      uint32_t ah[2][4], al[2][4], bh[4][2], bl[4][2];
#pragma unroll
      for (int mt = 0; mt < 2; mt++) {
        ldsm_x4(ah[mt][0], ah[mt][1], ah[mt][2], ah[mt][3],
                sb + a_off[mt] + kbo);
        ldsm_x4(al[mt][0], al[mt][1], al[mt][2], al[mt][3],
                sb + 18432 + a_off[mt] + kbo);
      }
#pragma unroll
      for (int gg = 0; gg < 2; gg++) {
        ldsm_x4(bh[gg * 2][0], bh[gg * 2][1], bh[gg * 2 + 1][0],
                bh[gg * 2 + 1][1], sb + 36864 + b_off[gg] + kbo);
        ldsm_x4(bl[gg * 2][0], bl[gg * 2][1], bl[gg * 2 + 1][0],
                bl[gg * 2 + 1][1], sb + 46080 + b_off[gg] + kbo);
      }
#pragma unroll
      for (int mt = 0; mt < 2; mt++)
#pragma unroll
        for (int nt = 0; nt < 4; nt++) {
          mma_bf16(acc[mt][nt], ah[mt], bh[nt]);
          mma_bf16(acc[mt][nt], ah[mt], bl[nt]);
          mma_bf16(acc[mt][nt], al[mt], bh[nt]);
        }
    }
  }

  // epilogue: bias + store (float2 per fragment row)
  const int h = j0 >> 6;
#pragma unroll
  for (int mt = 0; mt < 2; mt++) {
    const int row0 = i0 + wm * 32 + mt * 16 + g;
    const int row1 = row0 + 8;
#pragma unroll
    for (int nt = 0; nt < 4; nt++) {
      const int col = j0 + wn * 32 + nt * 8 + 2 * tg;
      const float2 bv = *(const float2*)(bias + col);
      float2 v0, v1;
      v0.x = acc[mt][nt][0] + bv.x; v0.y = acc[mt][nt][1] + bv.y;
      v1.x = acc[mt][nt][2] + bv.x; v1.y = acc[mt][nt][3] + bv.y;
      if (MODE == 0) {
        const int ch = col & 63;
        const int bb0 = row0 >> 11, s0 = row0 & 2047;
        const int bb1 = row1 >> 11, s1 = row1 & 2047;
        *(float2*)(out + ((size_t)(bb0 * kH + h) * kS + s0) * kHD + ch) = v0;
        *(float2*)(out + ((size_t)(bb1 * kH + h) * kS + s1) * kHD + ch) = v1;
      } else {
        *(float2*)(out + (size_t)row0 * kD + col) = v0;
        *(float2*)(out + (size_t)row1 * kD + col) = v1;
      }
    }
  }
}

// ---------------------------------------------------------------------------
// Fused causal attention (fp32 FFMA; mma.sync port planned next round)
// ---------------------------------------------------------------------------
__global__ void __launch_bounds__(256, 2) attn_kernel(float* __restrict__ attnW) {
  extern __shared__ float sm[];
  float(*Qs)[68] = (float(*)[68])sm;                // 128 x 68
  float(*Ks)[68] = (float(*)[68])(sm + 128 * 68);   // 64 x 68
  float(*Vt)[68] = (float(*)[68])(sm + 192 * 68);   // 64 x 68 (transposed)
  float(*Ps)[68] = (float(*)[68])(sm + 256 * 68);   // 128 x 68
  float* m_s  = sm + 384 * 68;
  float* li_s = m_s + 128;
  float* redm = (float*)Ps;
  float* redl = redm + 1024;

  const int t = threadIdx.x, lane = t & 31, w = t >> 5;
  const int q0 = blockIdx.x * 128;
  const int bh = blockIdx.y;
  const int b = bh >> 4, h = bh & 15;
  const float* qp = g_q + (size_t)bh * kS * kHD;
  const float* kp = g_k + (size_t)bh * kS * kHD;
  const float* vp = g_v + (size_t)bh * kS * kHD;
  float* aw = attnW + (size_t)bh * kS * kS;

#pragma unroll
  for (int p = 0; p < 8; p++) {
    int f = t + p * 256, r = f >> 4, c4 = f & 15;
    *(float4*)&Qs[r][c4 * 4] =
        *(const float4*)(qp + (size_t)(q0 + r) * kHD + c4 * 4);
  }

  float m_r[4], l_r[4];
#pragma unroll
  for (int ii = 0; ii < 4; ii++) { m_r[ii] = -1e30f; l_r[ii] = 0.f; }

  const int nkt = q0 / 64 + 2;

  // ---- Phase A ----
  for (int kt = 0; kt < nkt; kt++) {
    __syncthreads();
#pragma unroll
    for (int p = 0; p < 4; p++) {
      int f = t + p * 256, r = f >> 4, c4 = f & 15;
      *(float4*)&Ks[r][c4 * 4] =
          *(const float4*)(kp + (size_t)(kt * 64 + r) * kHD + c4 * 4);
    }
    __syncthreads();
    float sv[4][8];
#pragma unroll
    for (int ii = 0; ii < 4; ii++)
#pragma unroll
      for (int jj = 0; jj < 8; jj++) sv[ii][jj] = 0.f;
#pragma unroll
    for (int k = 0; k < 64; k += 4) {
      float4 af[4], bf[8];
#pragma unroll
      for (int ii = 0; ii < 4; ii++) af[ii] = *(float4*)&Qs[lane + 32 * ii][k];
#pragma unroll
      for (int jj = 0; jj < 8; jj++) bf[jj] = *(float4*)&Ks[w + 8 * jj][k];
#pragma unroll
      for (int ii = 0; ii < 4; ii++)
#pragma unroll
        for (int jj = 0; jj < 8; jj++) {
          sv[ii][jj] = fmaf(af[ii].x, bf[jj].x, sv[ii][jj]);
          sv[ii][jj] = fmaf(af[ii].y, bf[jj].y, sv[ii][jj]);
          sv[ii][jj] = fmaf(af[ii].z, bf[jj].z, sv[ii][jj]);
          sv[ii][jj] = fmaf(af[ii].w, bf[jj].w, sv[ii][jj]);
        }
    }
#pragma unroll
    for (int ii = 0; ii < 4; ii++) {
      int qq = q0 + lane + 32 * ii;
      float tmax = -1e30f;
#pragma unroll
      for (int jj = 0; jj < 8; jj++) {
        int kcol = kt * 64 + w + 8 * jj;
        float s = sv[ii][jj] * INV_SCALE;
        if (kcol > qq) s = -1e30f;
        sv[ii][jj] = s;
        tmax = fmaxf(tmax, s);
        Ps[lane + 32 * ii][w + 8 * jj] = s;
      }
      float mn = fmaxf(m_r[ii], tmax);
      float corr = __expf(m_r[ii] - mn);
      float ps = 0.f;
#pragma unroll
      for (int jj = 0; jj < 8; jj++) ps += __expf(sv[ii][jj] - mn);
      l_r[ii] = l_r[ii] * corr + ps;
      m_r[ii] = mn;
    }
    __syncthreads();
#pragma unroll
    for (int p = 0; p < 8; p++) {
      int f = t + p * 256, r = f >> 4, c4 = f & 15;
      *(float4*)(aw + (size_t)(q0 + r) * kS + kt * 64 + c4 * 4) =
          *(float4*)&Ps[r][c4 * 4];
    }
  }
  __syncthreads();

#pragma unroll
  for (int ii = 0; ii < 4; ii++) {
    redm[w * 128 + lane + 32 * ii] = m_r[ii];
    redl[w * 128 + lane + 32 * ii] = l_r[ii];
  }
  __syncthreads();
  if (t < 128) {
    float m = -1e30f;
#pragma unroll
    for (int ww = 0; ww < 8; ww++) m = fmaxf(m, redm[ww * 128 + t]);
    float l = 0.f;
#pragma unroll
    for (int ww = 0; ww < 8; ww++)
      l += redl[ww * 128 + t] * __expf(redm[ww * 128 + t] - m);
    m_s[t] = m;
    li_s[t] = 1.f / l;
  }
  __syncthreads();

  {
    int width4 = (kS - nkt * 64) >> 2;
    if (width4 > 0) {
      float4 z = make_float4(0.f, 0.f, 0.f, 0.f);
      for (int f = t; f < 128 * width4; f += 256) {
        int r = f / width4, c = f - r * width4;
        *(float4*)(aw + (size_t)(q0 + r) * kS + nkt * 64 + c * 4) = z;
      }
    }
  }

  float o[4][8];
#pragma unroll
  for (int ii = 0; ii < 4; ii++)
#pragma unroll
    for (int jj = 0; jj < 8; jj++) o[ii][jj] = 0.f;

  // ---- Phase B ----
  for (int kt = 0; kt < nkt; kt++) {
    __syncthreads();
#pragma unroll
    for (int p = 0; p < 4; p++) {
      int idx = t + p * 256;
      int dv = idx & 63, kq = idx >> 6;
#pragma unroll
      for (int e = 0; e < 4; e++)
        Vt[dv][kq * 4 + e] = vp[(size_t)(kt * 64 + kq * 4 + e) * kHD + dv];
    }
#pragma unroll
    for (int p = 0; p < 8; p++) {
      int f = t + p * 256, r = f >> 4, c4 = f & 15;
      size_t off = (size_t)(q0 + r) * kS + kt * 64 + c4 * 4;
      float4 s4 = *(const float4*)(aw + off);
      float m = m_s[r], li = li_s[r];
      float4 pv;
      pv.x = __expf(s4.x - m) * li;
      pv.y = __expf(s4.y - m) * li;
      pv.z = __expf(s4.z - m) * li;
      pv.w = __expf(s4.w - m) * li;
      *(float4*)&Ps[r][c4 * 4] = pv;
      *(float4*)(aw + off) = pv;
    }
    __syncthreads();
#pragma unroll
    for (int k = 0; k < 64; k += 4) {
      float4 af[4], bf[8];
#pragma unroll
      for (int ii = 0; ii < 4; ii++) af[ii] = *(float4*)&Ps[lane + 32 * ii][k];
#pragma unroll
      for (int jj = 0; jj < 8; jj++) bf[jj] = *(float4*)&Vt[w + 8 * jj][k];
#pragma unroll
      for (int ii = 0; ii < 4; ii++)
#pragma unroll
        for (int jj = 0; jj < 8; jj++) {
          o[ii][jj] = fmaf(af[ii].x, bf[jj].x, o[ii][jj]);
          o[ii][jj] = fmaf(af[ii].y, bf[jj].y, o[ii][jj]);
          o[ii][jj] = fmaf(af[ii].z, bf[jj].z, o[ii][jj]);
          o[ii][jj] = fmaf(af[ii].w, bf[jj].w, o[ii][jj]);
        }
    }
  }
  __syncthreads();
#pragma unroll
  for (int ii = 0; ii < 4; ii++)
#pragma unroll
    for (int jj = 0; jj < 8; jj++) Qs[lane + 32 * ii][w + 8 * jj] = o[ii][jj];
  __syncthreads();
#pragma unroll
  for (int p = 0; p < 8; p++) {
    int f = t + p * 256, r = f >> 4, c4 = f & 15;
    *(float4*)(g_ao + ((size_t)(b * kS + q0 + r)) * kD + h * kHD + c4 * 4) =
        *(float4*)&Qs[r][c4 * 4];
  }
}

// ---------------------------------------------------------------------------
extern "C" void kernel_launch(void* const* d_in, const int* in_sizes, int n_in,
                              void* d_out, int out_size) {
  (void)in_sizes; (void)n_in;
  const float* query = (const float*)d_in[0];
  const float* key_  = (const float*)d_in[1];
  const float* value = (const float*)d_in[2];
  // d_in[3] = causal mask (bool) — implied by indices, not read
  const float* Wq = (const float*)d_in[4];
  const float* bq = (const float*)d_in[5];
  const float* Wk = (const float*)d_in[6];
  const float* bk = (const float*)d_in[7];
  const float* Wv = (const float*)d_in[8];
  const float* bv = (const float*)d_in[9];
  const float* Wo = (const float*)d_in[10];
  const float* bo = (const float*)d_in[11];
  float* out = (float*)d_out;

  float *pq, *pk, *pv, *pao, *pfb;
  __nv_bfloat16 *pxh, *pxl, *pwh, *pwl;
  cudaGetSymbolAddress((void**)&pq, g_q);
  cudaGetSymbolAddress((void**)&pk, g_k);
  cudaGetSymbolAddress((void**)&pv, g_v);
  cudaGetSymbolAddress((void**)&pao, g_ao);
  cudaGetSymbolAddress((void**)&pfb, g_attn_fb);
  cudaGetSymbolAddress((void**)&pxh, g_xhi);
  cudaGetSymbolAddress((void**)&pxl, g_xlo);
  cudaGetSymbolAddress((void**)&pwh, g_whi);
  cudaGetSymbolAddress((void**)&pwl, g_wlo);

  const size_t outElems = (size_t)kB * kS * kD;
  const size_t attnElems = (size_t)kB * kH * kS * kS;
  float* attnW = ((size_t)out_size >= outElems + attnElems)
                     ? (out + outElems)
                     : pfb;

  const int ATTN_SMEM = (384 * 68 + 256) * 4;  // 105472 B
  cudaFuncSetAttribute(proj_mma<0>,
                       cudaFuncAttributeMaxDynamicSharedMemorySize, PROJ_SMEM_B);
  cudaFuncSetAttribute(proj_mma<1>,
                       cudaFuncAttributeMaxDynamicSharedMemorySize, PROJ_SMEM_B);
  cudaFuncSetAttribute(attn_kernel,
                       cudaFuncAttributeMaxDynamicSharedMemorySize, ATTN_SMEM);

  const int XN4 = kM * kD / 4;   // 1,048,576
  const int WN4 = kD * kD / 4;   // 262,144
  dim3 gproj(kD / 64, kM / 128);   // (16, 32)
  dim3 gattn(kS / 128, kB * kH);   // (16, 32)

  // Q projection
  cvt_split<<<XN4 / 256, 256>>>(query, pxh, pxl, XN4);
  cvt_split<<<WN4 / 256, 256>>>(Wq, pwh, pwl, WN4);
  proj_mma<0><<<gproj, 256, PROJ_SMEM_B>>>(pxh, pxl, pwh, pwl, bq, pq);
  // K projection
  cvt_split<<<XN4 / 256, 256>>>(key_, pxh, pxl, XN4);
  cvt_split<<<WN4 / 256, 256>>>(Wk, pwh, pwl, WN4);
  proj_mma<0><<<gproj, 256, PROJ_SMEM_B>>>(pxh, pxl, pwh, pwl, bk, pk);
  // V projection
  cvt_split<<<XN4 / 256, 256>>>(value, pxh, pxl, XN4);
  cvt_split<<<WN4 / 256, 256>>>(Wv, pwh, pwl, WN4);
  proj_mma<0><<<gproj, 256, PROJ_SMEM_B>>>(pxh, pxl, pwh, pwl, bv, pv);
  // attention
  attn_kernel<<<gattn, 256, ATTN_SMEM>>>(attnW);
  // output projection
  cvt_split<<<XN4 / 256, 256>>>(pao, pxh, pxl, XN4);
  cvt_split<<<WN4 / 256, 256>>>(Wo, pwh, pwl, WN4);
  proj_mma<1><<<gproj, 256, PROJ_SMEM_B>>>(pxh, pxl, pwh, pwl, bo, out);
}